// round 17
// baseline (speedup 1.0000x reference)
#include <cuda_runtime.h>
#include <cuda_bf16.h>
#include <math.h>
#include <stdint.h>

#define NN   50000
#define EE   800000
#define IND  128
#define HIDD 256
#define OUTD 40
#define TOT  (EE + NN)
#define BN_EPS 1e-5f

// ---------------- scratch (device globals: alloc-guard compliant) ----------------
__device__ __align__(16) __nv_bfloat16 g_t1[(size_t)NN * HIDD];
__device__ __align__(16) __nv_bfloat16 g_t2[(size_t)NN * HIDD];
__device__ float g_dinv[NN];
__device__ int   g_deg[NN];
__device__ int   g_cnt[NN];
__device__ int   g_cur[NN];
__device__ int   g_off[NN + 1];
__device__ int   g_row[EE];
__device__ int   g_col[EE];
__device__ __align__(16) int2 g_csr[TOT + 4];   // packed (col, w-bits)
__device__ float g_sum[HIDD];     // zero-init at load; bn_finalize re-zeroes after use
__device__ float g_sumsq[HIDD];
__device__ float g_bn_s[HIDD];
__device__ float g_bn_t[HIDD];

static inline int cdiv(int a, int b) { return (a + b - 1) / b; }

// ---------------- tf32 helpers ----------------
__device__ __forceinline__ float to_tf32(float x) {
    uint32_t u;
    asm("cvt.rna.tf32.f32 %0, %1;" : "=r"(u) : "f"(x));
    return __uint_as_float(u);
}

__device__ __forceinline__ void mma_tf32(float c[4], const uint32_t a[4], const uint32_t b[2]) {
    asm volatile(
        "mma.sync.aligned.m16n8k8.row.col.f32.tf32.tf32.f32 "
        "{%0,%1,%2,%3}, {%4,%5,%6,%7}, {%8,%9}, {%0,%1,%2,%3};\n"
        : "+f"(c[0]), "+f"(c[1]), "+f"(c[2]), "+f"(c[3])
        : "r"(a[0]), "r"(a[1]), "r"(a[2]), "r"(a[3]), "r"(b[0]), "r"(b[1]));
}

// ---------------- preprocessing ----------------
__global__ void k_convert_deg(const void* ei) {
    int e = blockIdx.x * blockDim.x + threadIdx.x;
    if (e >= EE) return;
    const unsigned long long* p8 = (const unsigned long long*)ei;
    bool is64 = true;
#pragma unroll
    for (int q = 0; q < 8; q++) is64 &= (p8[q] < (unsigned long long)NN);
    int r, c;
    if (is64) {
        const long long* p = (const long long*)ei;
        r = (int)p[e];
        c = (int)p[EE + e];
    } else {
        const int* p = (const int*)ei;
        r = p[e];
        c = p[EE + e];
    }
    g_row[e] = r;
    g_col[e] = c;
    atomicAdd(&g_deg[c], 1);
    atomicAdd(&g_cnt[r], 1);
}

__global__ void k_scan_dinv() {
    __shared__ int part[1024];
    int t = threadIdx.x;
    const int CH = (NN + 1023) / 1024;
    int b = t * CH;
    int e = min(NN, b + CH);
    int s = 0;
    for (int i = b; i < e; i++) {
        s += g_cnt[i] + 1;
        g_dinv[i] = rsqrtf((float)(g_deg[i] + 1));
        g_deg[i] = 0;
        g_cur[i] = 0;
    }
    part[t] = s;
    __syncthreads();
    for (int off = 1; off < 1024; off <<= 1) {
        int v = (t >= off) ? part[t - off] : 0;
        __syncthreads();
        part[t] += v;
        __syncthreads();
    }
    int pre = (t == 0) ? 0 : part[t - 1];
    for (int i = b; i < e; i++) {
        g_off[i] = pre;
        pre += g_cnt[i] + 1;
        g_cnt[i] = 0;
    }
    if (t == 1023) g_off[NN] = part[1023];
}

__global__ void k_fill() {
    int idx = blockIdx.x * blockDim.x + threadIdx.x;
    if (idx >= TOT) return;
    int r, c; float w;
    if (idx < EE) {
        r = g_row[idx];
        c = g_col[idx];
        w = g_dinv[r] * g_dinv[c];
    } else {
        r = idx - EE;
        c = r;
        float d = g_dinv[r];
        w = d * d;
    }
    int pos = g_off[r] + atomicAdd(&g_cur[r], 1);
    g_csr[pos] = make_int2(c, __float_as_int(w));
}

// ---------------- tensor-core GEMM: fp32 or bf16 A-in, tf32 mainloop, bf16 out ----------------
template <bool ABF16, bool FUSE, bool BIAS>
__global__ void __launch_bounds__(256, 3) k_gemm_tc(
    const void* __restrict__ Av, const float* __restrict__ B,
    const float* __restrict__ bias, __nv_bfloat16* __restrict__ C,
    int M, int K, int Ncols)
{
    constexpr int BM = 128, BN = 64, BK = 32;
    constexpr int ASTR = 36, BSTR = 68;
    __shared__ float As[BM * ASTR];
    __shared__ float Bs[BK * BSTR];

    const int tid  = threadIdx.x;
    const int warp = tid >> 5, lane = tid & 31;
    const int gid  = lane >> 2, tg = lane & 3;
    const int wm   = (warp & 3) * 32;
    const int wn   = (warp >> 2) * 32;
    const int bm   = blockIdx.y * BM, bn = blockIdx.x * BN;

    float c[2][4][4];
#pragma unroll
    for (int i = 0; i < 2; i++)
#pragma unroll
        for (int j = 0; j < 4; j++)
#pragma unroll
            for (int q = 0; q < 4; q++) c[i][j][q] = 0.f;

    // staging registers (one path used per instantiation)
    float4 aregf[4];
    uint4  aregb[2];
    float  breg[8];

    if constexpr (ABF16) {
        const __nv_bfloat16* A = (const __nv_bfloat16*)Av;
#pragma unroll
        for (int r = 0; r < 2; r++) {
            int idx = tid + r * 256;
            int m = idx >> 2, c8 = idx & 3;
            int gm = bm + m;
            aregb[r] = make_uint4(0u, 0u, 0u, 0u);
            if (gm < M) aregb[r] = *reinterpret_cast<const uint4*>(A + (size_t)gm * K + c8 * 8);
        }
    } else {
        const float* A = (const float*)Av;
#pragma unroll
        for (int r = 0; r < 4; r++) {
            int idx = tid + r * 256;
            int m = idx >> 3, c4 = idx & 7;
            int gm = bm + m;
            aregf[r] = make_float4(0.f, 0.f, 0.f, 0.f);
            if (gm < M) aregf[r] = *reinterpret_cast<const float4*>(A + (size_t)gm * K + c4 * 4);
        }
    }
#pragma unroll
    for (int r = 0; r < 8; r++) {
        int idx = tid + r * 256;
        int kk = idx >> 6, n = idx & 63;
        breg[r] = (bn + n < Ncols) ? B[(size_t)kk * Ncols + bn + n] : 0.f;
    }

    for (int k0 = 0; k0 < K; k0 += BK) {
        // ---- stage A to smem (FUSE + tf32) ----
        if constexpr (ABF16) {
#pragma unroll
            for (int r = 0; r < 2; r++) {
                int idx = tid + r * 256;
                int m = idx >> 2, c8 = idx & 3;
                const uint32_t* u = &aregb[r].x;
                float f[8];
#pragma unroll
                for (int j = 0; j < 4; j++) {
                    float2 p = __bfloat1622float2(
                        *reinterpret_cast<const __nv_bfloat162*>(&u[j]));
                    f[2 * j] = p.x;
                    f[2 * j + 1] = p.y;
                }
                if (FUSE) {
                    int gk = k0 + c8 * 8;
#pragma unroll
                    for (int j = 0; j < 8; j++)
                        f[j] = fmaxf(0.f, fmaf(f[j], g_bn_s[gk + j], g_bn_t[gk + j]));
                }
                *reinterpret_cast<float4*>(&As[m * ASTR + c8 * 8]) =
                    make_float4(to_tf32(f[0]), to_tf32(f[1]), to_tf32(f[2]), to_tf32(f[3]));
                *reinterpret_cast<float4*>(&As[m * ASTR + c8 * 8 + 4]) =
                    make_float4(to_tf32(f[4]), to_tf32(f[5]), to_tf32(f[6]), to_tf32(f[7]));
            }
        } else {
#pragma unroll
            for (int r = 0; r < 4; r++) {
                int idx = tid + r * 256;
                int m = idx >> 3, c4 = idx & 7;
                float4 v = aregf[r];
                if (FUSE) {
                    int gk = k0 + c4 * 4;
                    v.x = fmaxf(0.f, fmaf(v.x, g_bn_s[gk + 0], g_bn_t[gk + 0]));
                    v.y = fmaxf(0.f, fmaf(v.y, g_bn_s[gk + 1], g_bn_t[gk + 1]));
                    v.z = fmaxf(0.f, fmaf(v.z, g_bn_s[gk + 2], g_bn_t[gk + 2]));
                    v.w = fmaxf(0.f, fmaf(v.w, g_bn_s[gk + 3], g_bn_t[gk + 3]));
                }
                *reinterpret_cast<float4*>(&As[m * ASTR + c4 * 4]) =
                    make_float4(to_tf32(v.x), to_tf32(v.y), to_tf32(v.z), to_tf32(v.w));
            }
        }
#pragma unroll
        for (int r = 0; r < 8; r++) {
            int idx = tid + r * 256;
            int kk = idx >> 6, n = idx & 63;
            Bs[kk * BSTR + n] = to_tf32(breg[r]);
        }
        __syncthreads();

        // ---- prefetch next tile ----
        if (k0 + BK < K) {
            int kn = k0 + BK;
            if constexpr (ABF16) {
                const __nv_bfloat16* A = (const __nv_bfloat16*)Av;
#pragma unroll
                for (int r = 0; r < 2; r++) {
                    int idx = tid + r * 256;
                    int m = idx >> 2, c8 = idx & 3;
                    int gm = bm + m;
                    aregb[r] = make_uint4(0u, 0u, 0u, 0u);
                    if (gm < M) aregb[r] = *reinterpret_cast<const uint4*>(A + (size_t)gm * K + kn + c8 * 8);
                }
            } else {
                const float* A = (const float*)Av;
#pragma unroll
                for (int r = 0; r < 4; r++) {
                    int idx = tid + r * 256;
                    int m = idx >> 3, c4 = idx & 7;
                    int gm = bm + m;
                    aregf[r] = make_float4(0.f, 0.f, 0.f, 0.f);
                    if (gm < M) aregf[r] = *reinterpret_cast<const float4*>(A + (size_t)gm * K + kn + c4 * 4);
                }
            }
#pragma unroll
            for (int r = 0; r < 8; r++) {
                int idx = tid + r * 256;
                int kk = idx >> 6, n = idx & 63;
                breg[r] = (bn + n < Ncols) ? B[(size_t)(kn + kk) * Ncols + bn + n] : 0.f;
            }
        }

        // ---- compute ----
#pragma unroll
        for (int kc = 0; kc < 4; kc++) {
            int kb = kc * 8 + tg;
            uint32_t a[2][4], b[4][2];
#pragma unroll
            for (int am = 0; am < 2; am++) {
                int mr = wm + am * 16 + gid;
                a[am][0] = __float_as_uint(As[mr * ASTR + kb]);
                a[am][1] = __float_as_uint(As[(mr + 8) * ASTR + kb]);
                a[am][2] = __float_as_uint(As[mr * ASTR + kb + 4]);
                a[am][3] = __float_as_uint(As[(mr + 8) * ASTR + kb + 4]);
            }
#pragma unroll
            for (int bi = 0; bi < 4; bi++) {
                int nc = wn + bi * 8 + gid;
                b[bi][0] = __float_as_uint(Bs[kb * BSTR + nc]);
                b[bi][1] = __float_as_uint(Bs[(kb + 4) * BSTR + nc]);
            }
#pragma unroll
            for (int am = 0; am < 2; am++)
#pragma unroll
                for (int bi = 0; bi < 4; bi++)
                    mma_tf32(c[am][bi], a[am], b[bi]);
        }
        __syncthreads();
    }

#pragma unroll
    for (int am = 0; am < 2; am++) {
#pragma unroll
        for (int bi = 0; bi < 4; bi++) {
            int row = bm + wm + am * 16 + gid;
            int col = bn + wn + bi * 8 + 2 * tg;
            float bv0 = 0.f, bv1 = 0.f;
            if (BIAS) {
                if (col < Ncols)     bv0 = bias[col];
                if (col + 1 < Ncols) bv1 = bias[col + 1];
            }
            float v0 = c[am][bi][0] + bv0, v1 = c[am][bi][1] + bv1;
            float v2 = c[am][bi][2] + bv0, v3 = c[am][bi][3] + bv1;
            if (row < M && col < Ncols)
                *reinterpret_cast<__nv_bfloat162*>(C + (size_t)row * Ncols + col) =
                    __floats2bfloat162_rn(v0, v1);
            if (row + 8 < M && col < Ncols)
                *reinterpret_cast<__nv_bfloat162*>(C + (size_t)(row + 8) * Ncols + col) =
                    __floats2bfloat162_rn(v2, v3);
        }
    }
}

// ---------------- bf16 aggregation (packed CSR): gather bf16, fp32 accum, bf16 out ----------------
template <int F, int RPB, bool BIAS>
__global__ void __launch_bounds__(32 * RPB) k_agg_bf16(
    const __nv_bfloat16* __restrict__ h, const float* __restrict__ bias,
    __nv_bfloat16* __restrict__ out)
{
    constexpr int V = F / 32;
    constexpr int V2 = V / 2;
    int i = blockIdx.x * RPB + threadIdx.x / 32;
    int t = threadIdx.x % 32;
    if (i >= NN) return;
    float acc[V];
#pragma unroll
    for (int j = 0; j < V; j++) acc[j] = 0.f;
    int p = g_off[i], end = g_off[i + 1];

#define GATHER_BF(cc, ww)                                                           \
    {                                                                               \
        uint32_t wreg[V2];                                                          \
        const __nv_bfloat16* src = h + (size_t)(cc) * F + t * V;                    \
        if constexpr (V2 == 2) {                                                    \
            uint2 u = *reinterpret_cast<const uint2*>(src);                         \
            wreg[0] = u.x; wreg[1] = u.y;                                           \
        } else {                                                                    \
            uint4 u = *reinterpret_cast<const uint4*>(src);                         \
            wreg[0] = u.x; wreg[1] = u.y; wreg[2] = u.z; wreg[3] = u.w;             \
        }                                                                           \
        _Pragma("unroll")                                                           \
        for (int j = 0; j < V2; j++) {                                              \
            float2 f = __bfloat1622float2(                                          \
                *reinterpret_cast<const __nv_bfloat162*>(&wreg[j]));                \
            acc[2 * j]     = fmaf((ww), f.x, acc[2 * j]);                           \
            acc[2 * j + 1] = fmaf((ww), f.y, acc[2 * j + 1]);                       \
        }                                                                           \
    }

    while (p < end && (p & 3)) {
        int2 e0 = g_csr[p];
        GATHER_BF(e0.x, __int_as_float(e0.y));
        p++;
    }
    for (; p + 3 < end; p += 4) {
        int4 e01 = *reinterpret_cast<const int4*>(&g_csr[p]);
        int4 e23 = *reinterpret_cast<const int4*>(&g_csr[p + 2]);
        GATHER_BF(e01.x, __int_as_float(e01.y));
        GATHER_BF(e01.z, __int_as_float(e01.w));
        GATHER_BF(e23.x, __int_as_float(e23.y));
        GATHER_BF(e23.z, __int_as_float(e23.w));
    }
    for (; p < end; p++) {
        int2 e0 = g_csr[p];
        GATHER_BF(e0.x, __int_as_float(e0.y));
    }
#undef GATHER_BF

    uint32_t packed[V2];
#pragma unroll
    for (int j = 0; j < V; j++)
        if (BIAS) acc[j] += bias[t * V + j];
#pragma unroll
    for (int j = 0; j < V2; j++) {
        __nv_bfloat162 pb = __floats2bfloat162_rn(acc[2 * j], acc[2 * j + 1]);
        packed[j] = *reinterpret_cast<uint32_t*>(&pb);
    }
    __nv_bfloat16* dst = out + (size_t)i * F + t * V;
    if constexpr (V2 == 2) {
        *reinterpret_cast<uint2*>(dst) = make_uint2(packed[0], packed[1]);
    } else {
        *reinterpret_cast<uint4*>(dst) = make_uint4(packed[0], packed[1], packed[2], packed[3]);
    }
}

// ---------------- bf16 batchnorm stats ----------------
__global__ void __launch_bounds__(256) k_stats_bf16(const __nv_bfloat16* __restrict__ h) {
    int c2 = threadIdx.x;
    int pair = c2 & 127;
    int half = c2 >> 7;
    int rows_per_block = (NN + gridDim.x - 1) / gridDim.x;
    int r0 = blockIdx.x * rows_per_block + half * (rows_per_block / 2);
    int r1 = min(NN, (half ? blockIdx.x * rows_per_block + rows_per_block
                           : blockIdx.x * rows_per_block + rows_per_block / 2));
    float s0 = 0.f, s1 = 0.f, q0 = 0.f, q1 = 0.f;
    for (int r = r0; r < r1; r++) {
        float2 f = __bfloat1622float2(
            *reinterpret_cast<const __nv_bfloat162*>(h + (size_t)r * HIDD + pair * 2));
        s0 += f.x; q0 = fmaf(f.x, f.x, q0);
        s1 += f.y; q1 = fmaf(f.y, f.y, q1);
    }
    atomicAdd(&g_sum[pair * 2 + 0], s0); atomicAdd(&g_sumsq[pair * 2 + 0], q0);
    atomicAdd(&g_sum[pair * 2 + 1], s1); atomicAdd(&g_sumsq[pair * 2 + 1], q1);
}

// ---------------- fused layer-3 bf16 agg + log_softmax (packed CSR, warp per row) ----------------
__global__ void __launch_bounds__(128) k_agg_softmax_bf16(
    const __nv_bfloat16* __restrict__ h, const float* __restrict__ bias,
    float* __restrict__ out)
{
    int i = blockIdx.x * 4 + (threadIdx.x >> 5);
    int t = threadIdx.x & 31;
    if (i >= NN) return;
    float a0 = 0.f, a1 = 0.f;
    int p = g_off[i], end = g_off[i + 1];
    bool act = (t < OUTD / 2);
    for (; p + 1 < end; p += 2) {
        int4 e01 = ((p & 1) == 0)
            ? *reinterpret_cast<const int4*>(&g_csr[p])
            : make_int4(g_csr[p].x, g_csr[p].y, g_csr[p + 1].x, g_csr[p + 1].y);
        int   c0 = e01.x, c1 = e01.z;
        float w0 = __int_as_float(e01.y);
        float w1 = __int_as_float(e01.w);
        if (act) {
            float2 f0 = __bfloat1622float2(
                *reinterpret_cast<const __nv_bfloat162*>(h + (size_t)c0 * OUTD + 2 * t));
            float2 f1 = __bfloat1622float2(
                *reinterpret_cast<const __nv_bfloat162*>(h + (size_t)c1 * OUTD + 2 * t));
            a0 = fmaf(w0, f0.x, fmaf(w1, f1.x, a0));
            a1 = fmaf(w0, f0.y, fmaf(w1, f1.y, a1));
        }
    }
    if (p < end && act) {
        int2 e0 = g_csr[p];
        float w0 = __int_as_float(e0.y);
        float2 f0 = __bfloat1622float2(
            *reinterpret_cast<const __nv_bfloat162*>(h + (size_t)e0.x * OUTD + 2 * t));
        a0 = fmaf(w0, f0.x, a0);
        a1 = fmaf(w0, f0.y, a1);
    }
    float v0 = act ? (a0 + bias[2 * t])     : -INFINITY;
    float v1 = act ? (a1 + bias[2 * t + 1]) : -INFINITY;
    float m = fmaxf(v0, v1);
#pragma unroll
    for (int off = 16; off > 0; off >>= 1)
        m = fmaxf(m, __shfl_xor_sync(0xFFFFFFFFu, m, off));
    float s = act ? (expf(v0 - m) + expf(v1 - m)) : 0.f;
#pragma unroll
    for (int off = 16; off > 0; off >>= 1)
        s += __shfl_xor_sync(0xFFFFFFFFu, s, off);
    float l = m + logf(s);
    if (act) {
        out[(size_t)i * OUTD + 2 * t]     = v0 - l;
        out[(size_t)i * OUTD + 2 * t + 1] = v1 - l;
    }
}

// ---------------- bn finalize (reads stats, re-zeroes for next pass) ----------------
__global__ void k_bn_finalize(const float* __restrict__ gamma,
                              const float* __restrict__ beta) {
    int c = threadIdx.x;
    float mu = g_sum[c] * (1.f / NN);
    float var = g_sumsq[c] * (1.f / NN) - mu * mu;
    float rstd = rsqrtf(var + BN_EPS);
    float sc = rstd * gamma[c];
    g_bn_s[c] = sc;
    g_bn_t[c] = beta[c] - mu * sc;
    g_sum[c] = 0.f;
    g_sumsq[c] = 0.f;
}

// ---------------- launch ----------------
extern "C" void kernel_launch(void* const* d_in, const int* in_sizes, int n_in,
                              void* d_out, int out_size) {
    const float* x     = (const float*)d_in[0];
    const void*  ei    = d_in[1];
    const float* W1    = (const float*)d_in[2];
    const float* b1    = (const float*)d_in[3];
    const float* W2    = (const float*)d_in[4];
    const float* b2    = (const float*)d_in[5];
    const float* W3    = (const float*)d_in[6];
    const float* b3    = (const float*)d_in[7];
    const float* gamma = (const float*)d_in[8];
    const float* beta  = (const float*)d_in[9];
    float* out = (float*)d_out;

    __nv_bfloat16 *t1, *t2;
    cudaGetSymbolAddress((void**)&t1, g_t1);
    cudaGetSymbolAddress((void**)&t2, g_t2);

    // preprocessing
    k_convert_deg<<<cdiv(EE, 256), 256>>>(ei);   // 0
    k_scan_dinv<<<1, 1024>>>();                  // 1
    k_fill<<<cdiv(TOT, 256), 256>>>();           // 2

    dim3 g256(4, cdiv(NN, 128));    // Ncols=256
    dim3 g40(1, cdiv(NN, 128));     // Ncols=40

    // layer 1: TRANSFORM-FIRST this round (measure the current GEMM at slot 3)
    k_gemm_tc<false, false, false><<<g256, 256>>>(x, W1, nullptr, t1, NN, IND, HIDD); // 3 <- profiled
    k_agg_bf16<HIDD, 4, true><<<cdiv(NN, 4), 128>>>(t1, b1, t2);                      // 4
    k_stats_bf16<<<256, 256>>>(t2);                                                   // 5
    k_bn_finalize<<<1, HIDD>>>(gamma, beta);                                          // 6

    // layer 2: GEMM bf16-A (BN+ReLU fused) -> bf16; agg bf16 -> bf16 + bias; stats
    k_gemm_tc<true, true, false><<<g256, 256>>>(t2, W2, nullptr, t1, NN, HIDD, HIDD); // 7
    k_agg_bf16<HIDD, 4, true><<<cdiv(NN, 4), 128>>>(t1, b2, t2);                      // 8
    k_stats_bf16<<<256, 256>>>(t2);                                                   // 9
    k_bn_finalize<<<1, HIDD>>>(gamma, beta);                                          // 10

    // layer 3: GEMM bf16-A (FUSE) -> bf16 logits; fused bf16 agg + log_softmax
    k_gemm_tc<true, true, false><<<g40, 256>>>(t2, W3, nullptr, t1, NN, HIDD, OUTD);  // 11
    k_agg_softmax_bf16<<<cdiv(NN, 4), 128>>>(t1, b3, out);                            // 12
}